// round 12
// baseline (speedup 1.0000x reference)
#include <cuda_runtime.h>
#include <cuda_bf16.h>
#include <math_constants.h>
#include <cstdint>

// VectorQuantizer GB300: single persistent kernel. mma.sync bf16 screen
// (fragment-packed B, raw-dot scores) + 3-slot register stash + noinline exact
// fp32 rescore + last-CTA finalize. latents [131072,64] f32, codebook [512,64] f32.
// out (f32): quantized_st[8388608] | codes[131072] | commitment | codebook_loss | perplexity

#define D        64
#define K        512
#define N_VEC    131072
#define TILE_M   128
#define N_TILES  (N_VEC / TILE_M)   // 1024
#define TPB      256
#define GRID     296

#define OUT_CODES (N_VEC * D)
#define OUT_SCAL  (OUT_CODES + N_VEC)
#define MARGIN    4e-3f
#define QMARGIN   (MARGIN + 4e-5f)

// ---- smem byte layout (dynamic; ~87KB -> 2 CTAs/SM) ----
#define SM_RED     0                       // 8 f32 -> pad 64
#define SM_X2      64                      // 128 f32 -> 576
#define SM_BESTK   576                     // 128 i32 -> 1088
#define SM_C2      1088                    // 512 f32 -> 3136
#define SM_HIST    3136                    // 512 i32 -> 5184
#define SM_A_BF16  5184                    // 128 x 144B -> 23616
#define SM_B0      23616                   // 64 ntiles x 32 lanes x 16B -> 56384
#define SM_B1      56384                   // same -> 89152
#define SM_TOTAL   89152

__device__ double g_mse_sum;   // static zero-init; last CTA resets
__device__ int    g_hist[K];
__device__ int    g_done;

__device__ __forceinline__ void mma16816(float& c0, float& c1, float& c2, float& c3,
                                         uint32_t a0, uint32_t a1, uint32_t a2, uint32_t a3,
                                         uint32_t b0, uint32_t b1) {
    asm volatile(
        "mma.sync.aligned.m16n8k16.row.col.f32.bf16.bf16.f32 "
        "{%0,%1,%2,%3}, {%4,%5,%6,%7}, {%8,%9}, {%0,%1,%2,%3};"
        : "+f"(c0), "+f"(c1), "+f"(c2), "+f"(c3)
        : "r"(a0), "r"(a1), "r"(a2), "r"(a3), "r"(b0), "r"(b1));
}

// Exact fp32 distance — byte-for-byte the Round-1 formula (rel_err 0.0).
__device__ __forceinline__ float exact_d2(const float* __restrict__ codebook,
                                          const float* __restrict__ x, float x2,
                                          const float* __restrict__ c2s, int col) {
    const float4* cr = (const float4*)(codebook + col * D);
    const float4* xr = (const float4*)x;
    float4 acc = make_float4(0.f, 0.f, 0.f, 0.f);
    #pragma unroll
    for (int i = 0; i < 16; i++) {
        float4 cc = cr[i];
        float4 xv = xr[i];
        acc.x = fmaf(xv.x, cc.x, acc.x); acc.y = fmaf(xv.y, cc.y, acc.y);
        acc.z = fmaf(xv.z, cc.z, acc.z); acc.w = fmaf(xv.w, cc.w, acc.w);
    }
    float dot = (acc.x + acc.y) + (acc.z + acc.w);
    return fmaf(-2.0f, dot, x2) + c2s[col];
}

#define SLOTF(t) __uint_as_float((t) & ~0x1FFu)
// 3-slot sorted register stash (by masked score; strict < keeps earliest col).
#define PUSH3(t0, t1, t2, s, col) do {                                       \
    uint32_t _pv = (__float_as_uint(s) & ~0x1FFu) | (unsigned)(col);         \
    float _fs = SLOTF(_pv);                                                  \
    if (_fs < SLOTF(t2)) {                                                   \
        if (_fs < SLOTF(t1)) {                                               \
            t2 = t1;                                                         \
            if (_fs < SLOTF(t0)) { t1 = t0; t0 = _pv; } else t1 = _pv;       \
        } else t2 = _pv;                                                     \
    }                                                                        \
} while (0)

// Rescore 3 slots vs threshold (or provably-correct fallback rescan).
// Returns packed lexicographic key: (f32 bits of d2) << 32 | col  (d2 > 0).
__device__ __noinline__ unsigned long long pick3(
    const float* __restrict__ codebook, const float* __restrict__ x,
    float x2, const float* __restrict__ c2s,
    uint32_t t0, uint32_t t1, uint32_t t2, float gthr, int tig)
{
    unsigned long long best = (0x7F800000ull << 32) | 0x1FFull;
    int nU = (SLOTF(t0) < gthr) + (SLOTF(t1) < gthr) + (SLOTF(t2) < gthr);
    if (nU < 3) {
        if (SLOTF(t0) < gthr) {
            int col = t0 & 0x1FF;
            float d2 = exact_d2(codebook, x, x2, c2s, col);
            unsigned long long p = ((unsigned long long)__float_as_uint(d2) << 32) | (unsigned)col;
            if (p < best) best = p;
        }
        if (SLOTF(t1) < gthr) {
            int col = t1 & 0x1FF;
            float d2 = exact_d2(codebook, x, x2, c2s, col);
            unsigned long long p = ((unsigned long long)__float_as_uint(d2) << 32) | (unsigned)col;
            if (p < best) best = p;
        }
        if (SLOTF(t2) < gthr) {
            int col = t2 & 0x1FF;
            float d2 = exact_d2(codebook, x, x2, c2s, col);
            unsigned long long p = ((unsigned long long)__float_as_uint(d2) << 32) | (unsigned)col;
            if (p < best) best = p;
        }
    } else {   // stash saturated: rescan this thread's 128 columns (rare)
        #pragma unroll 1
        for (int n = 0; n < 64; n++) {
            int col = n * 8 + tig * 2;
            float d2 = exact_d2(codebook, x, x2, c2s, col);
            unsigned long long p = ((unsigned long long)__float_as_uint(d2) << 32) | (unsigned)col;
            if (p < best) best = p;
            d2 = exact_d2(codebook, x, x2, c2s, col + 1);
            p = ((unsigned long long)__float_as_uint(d2) << 32) | (unsigned)(col + 1);
            if (p < best) best = p;
        }
    }
    return best;
}

__device__ __forceinline__ uint32_t pack2m(float a, float b) {
    __nv_bfloat162 h = __floats2bfloat162_rn(a, b);
    return *reinterpret_cast<uint32_t*>(&h);
}

__global__ __launch_bounds__(TPB, 2) void vq_main_kernel(
    const float* __restrict__ latents,
    const float* __restrict__ codebook,
    float* __restrict__ out)
{
    extern __shared__ char smc[];
    __shared__ int   s_isLast;
    __shared__ float s_ent[256];

    float* red     = (float*)(smc + SM_RED);
    float* x2s     = (float*)(smc + SM_X2);
    int*   bestksm = (int*)(smc + SM_BESTK);
    float* c2s     = (float*)(smc + SM_C2);
    int*   histsm  = (int*)(smc + SM_HIST);

    const int tid  = threadIdx.x;
    const int wid  = tid >> 5;
    const int lane = tid & 31;
    const int g    = lane >> 2;
    const int tig  = lane & 3;
    const int rowbase = wid * 16;

    // ---- one-time setup: hist, fragment-packed B = -2*cb bf16, c2 ----
    for (int k = tid; k < K; k += TPB) histsm[k] = 0;
    for (int idx = tid; idx < 64 * 32; idx += TPB) {
        int ntile = idx >> 5, ln = idx & 31;
        int gg = ln >> 2, tt = ln & 3;
        const float* cr = codebook + (ntile * 8 + gg) * D;
        uint4 u0, u1;
        u0.x = pack2m(-2.f * cr[ 0 + tt*2], -2.f * cr[ 0 + tt*2 + 1]);
        u0.y = pack2m(-2.f * cr[16 + tt*2], -2.f * cr[16 + tt*2 + 1]);
        u0.z = pack2m(-2.f * cr[32 + tt*2], -2.f * cr[32 + tt*2 + 1]);
        u0.w = pack2m(-2.f * cr[48 + tt*2], -2.f * cr[48 + tt*2 + 1]);
        u1.x = pack2m(-2.f * cr[ 8 + tt*2], -2.f * cr[ 8 + tt*2 + 1]);
        u1.y = pack2m(-2.f * cr[24 + tt*2], -2.f * cr[24 + tt*2 + 1]);
        u1.z = pack2m(-2.f * cr[40 + tt*2], -2.f * cr[40 + tt*2 + 1]);
        u1.w = pack2m(-2.f * cr[56 + tt*2], -2.f * cr[56 + tt*2 + 1]);
        *(uint4*)(smc + SM_B0 + idx * 16) = u0;
        *(uint4*)(smc + SM_B1 + idx * 16) = u1;
    }
    for (int k = tid; k < K; k += TPB) {   // Round-1-identical c2 formula
        const float4* row = (const float4*)(codebook + k * D);
        float4 a = make_float4(0.f, 0.f, 0.f, 0.f);
        #pragma unroll
        for (int i = 0; i < 16; i++) {
            float4 c = row[i];
            a.x = fmaf(c.x, c.x, a.x); a.y = fmaf(c.y, c.y, a.y);
            a.z = fmaf(c.z, c.z, a.z); a.w = fmaf(c.w, c.w, a.w);
        }
        c2s[k] = (a.x + a.y) + (a.z + a.w);
    }
    __syncthreads();

    float cta_msq = 0.f;

    for (int tile = blockIdx.x; tile < N_TILES; tile += GRID) {
        const float* tlat = latents + (size_t)tile * (TILE_M * D);

        // ---- 1. latent tile -> bf16 A operand in smem ----
        {
            const float4* gp = (const float4*)tlat;
            #pragma unroll
            for (int i = 0; i < 8; i++) {
                int idx = i * TPB + tid;
                float4 v = gp[idx];
                int row = idx >> 4, col = idx & 15;
                uint2 u;
                u.x = pack2m(v.x, v.y);
                u.y = pack2m(v.z, v.w);
                *(uint2*)(smc + SM_A_BF16 + row * 144 + col * 8) = u;
            }
        }

        // ---- 2. x2 per row (R1-identical chain, from global/L2) ----
        if (tid < TILE_M) {
            const float4* my = (const float4*)(tlat + tid * D);
            float4 a = make_float4(0.f, 0.f, 0.f, 0.f);
            #pragma unroll
            for (int i = 0; i < 16; i++) {
                float4 v = my[i];
                a.x = fmaf(v.x, v.x, a.x); a.y = fmaf(v.y, v.y, a.y);
                a.z = fmaf(v.z, v.z, a.z); a.w = fmaf(v.w, v.w, a.w);
            }
            x2s[tid] = (a.x + a.y) + (a.z + a.w);
        }
        __syncthreads();

        // ---- 3. A fragments for this warp's 16 rows ----
        uint32_t af[4][4];
        #pragma unroll
        for (int kt = 0; kt < 4; kt++) {
            int kb = kt * 32 + tig * 4;
            af[kt][0] = *(const uint32_t*)(smc + SM_A_BF16 + (rowbase + g)     * 144 + kb);
            af[kt][1] = *(const uint32_t*)(smc + SM_A_BF16 + (rowbase + g + 8) * 144 + kb);
            af[kt][2] = *(const uint32_t*)(smc + SM_A_BF16 + (rowbase + g)     * 144 + kb + 16);
            af[kt][3] = *(const uint32_t*)(smc + SM_A_BF16 + (rowbase + g + 8) * 144 + kb + 16);
        }

        // ---- 4. screen: raw -2*dot scores, running min + 3-slot stash ----
        float runA = CUDART_INF_F, runB = CUDART_INF_F;
        uint32_t a0 = 0x7F800000u, a1 = 0x7F800000u, a2 = 0x7F800000u;
        uint32_t e0 = 0x7F800000u, e1 = 0x7F800000u, e2 = 0x7F800000u;
        #pragma unroll 4
        for (int ntile = 0; ntile < 64; ntile++) {
            uint4 w0 = *(const uint4*)(smc + SM_B0 + (ntile * 32 + lane) * 16);
            uint4 w1 = *(const uint4*)(smc + SM_B1 + (ntile * 32 + lane) * 16);
            float p0 = 0.f, p1 = 0.f, p2 = 0.f, p3 = 0.f;
            float q0 = 0.f, q1 = 0.f, q2 = 0.f, q3 = 0.f;
            mma16816(p0, p1, p2, p3, af[0][0], af[0][1], af[0][2], af[0][3], w0.x, w1.x);
            mma16816(p0, p1, p2, p3, af[1][0], af[1][1], af[1][2], af[1][3], w0.y, w1.y);
            mma16816(q0, q1, q2, q3, af[2][0], af[2][1], af[2][2], af[2][3], w0.z, w1.z);
            mma16816(q0, q1, q2, q3, af[3][0], af[3][1], af[3][2], af[3][3], w0.w, w1.w);
            float s0 = p0 + q0, s1 = p1 + q1;   // raw score: d2 ~= x2 + s + c2
            float s2 = p2 + q2, s3 = p3 + q3;
            int col0 = ntile * 8 + tig * 2, col1 = col0 + 1;
            runA = fminf(runA, fminf(s0, s1));
            runB = fminf(runB, fminf(s2, s3));
            float thrA = runA + MARGIN, thrB = runB + MARGIN;
            if (s0 < thrA) PUSH3(a0, a1, a2, s0, col0);
            if (s1 < thrA) PUSH3(a0, a1, a2, s1, col1);
            if (s2 < thrB) PUSH3(e0, e1, e2, s2, col0);
            if (s3 < thrB) PUSH3(e0, e1, e2, s3, col1);
        }

        // ---- 5. final row min (quad) + rescore via noinline helper ----
        #pragma unroll
        for (int off = 1; off <= 2; off <<= 1) {
            runA = fminf(runA, __shfl_xor_sync(0xFFFFFFFFu, runA, off));
            runB = fminf(runB, __shfl_xor_sync(0xFFFFFFFFu, runB, off));
        }
        const int rowA = rowbase + g, rowB = rowbase + g + 8;
        unsigned long long pA = pick3(codebook, tlat + rowA * D, x2s[rowA], c2s,
                                      a0, a1, a2, runA + QMARGIN, tig);
        unsigned long long pB = pick3(codebook, tlat + rowB * D, x2s[rowB], c2s,
                                      e0, e1, e2, runB + QMARGIN, tig);
        #pragma unroll
        for (int off = 1; off <= 2; off <<= 1) {
            unsigned long long o = __shfl_xor_sync(0xFFFFFFFFu, pA, off);
            if (o < pA) pA = o;
            o = __shfl_xor_sync(0xFFFFFFFFu, pB, off);
            if (o < pB) pB = o;
        }
        if (tig == 0) {
            bestksm[rowA] = (int)(pA & 0x1FF);
            bestksm[rowB] = (int)(pB & 0x1FF);
        }
        __syncthreads();

        // ---- 6. codes + histogram ----
        if (tid < TILE_M) {
            int bk = bestksm[tid];
            out[OUT_CODES + tile * TILE_M + tid] = (float)bk;
            atomicAdd(&histsm[bk], 1);
        }

        // ---- 7. quantized_st + mse (R1-identical math; x from L2) ----
        float msq = 0.f;
        {
            float4* og = (float4*)out + (size_t)tile * (TILE_M * D / 4);
            const float4* gp = (const float4*)tlat;
            #pragma unroll
            for (int i = 0; i < 8; i++) {
                int idx = i * TPB + tid;
                int row = idx >> 4, col = idx & 15;
                float4 xv = gp[idx];
                float4 c = ((const float4*)(codebook + bestksm[row] * D))[col];
                float4 o;
                o.x = xv.x + (c.x - xv.x); o.y = xv.y + (c.y - xv.y);
                o.z = xv.z + (c.z - xv.z); o.w = xv.w + (c.w - xv.w);
                float dx = xv.x - c.x; msq = fmaf(dx, dx, msq);
                dx = xv.y - c.y; msq = fmaf(dx, dx, msq);
                dx = xv.z - c.z; msq = fmaf(dx, dx, msq);
                dx = xv.w - c.w; msq = fmaf(dx, dx, msq);
                og[idx] = o;
            }
        }

        // ---- 8. msq block-reduce ----
        #pragma unroll
        for (int s = 16; s > 0; s >>= 1) msq += __shfl_xor_sync(0xFFFFFFFFu, msq, s);
        if (lane == 0) red[wid] = msq;
        __syncthreads();
        if (tid == 0) {
            float bsum = 0.f;
            #pragma unroll
            for (int w = 0; w < 8; w++) bsum += red[w];
            cta_msq += bsum;
        }
        __syncthreads();   // protect smem reuse next tile
    }

    // ---- flush per-CTA hist + mse ----
    for (int k = tid; k < K; k += TPB) {
        int h = histsm[k];
        if (h) atomicAdd(&g_hist[k], h);
    }
    if (tid == 0) atomicAdd(&g_mse_sum, (double)cta_msq);

    // ---- last-CTA finalize (scalars + reset for graph replay) ----
    __threadfence();
    if (tid == 0) {
        int c = atomicAdd(&g_done, 1);
        s_isLast = (c == GRID - 1);
    }
    __syncthreads();
    if (s_isLast) {
        float cnt0 = (float)g_hist[tid];
        float p0v  = cnt0 / (float)N_VEC;
        float t0v  = -p0v * logf(p0v + 1e-10f);
        float cnt1 = (float)g_hist[tid + 256];
        float p1v  = cnt1 / (float)N_VEC;
        float t1v  = -p1v * logf(p1v + 1e-10f);
        s_ent[tid] = t0v + t1v;   // same pairing as 512-tree step 1
        __syncthreads();
        for (int s = 128; s > 0; s >>= 1) {
            if (tid < s) s_ent[tid] += s_ent[tid + s];
            __syncthreads();
        }
        if (tid == 0) {
            float perplexity = expf(s_ent[0]);
            double mse = g_mse_sum / (double)(N_VEC * D);
            out[OUT_SCAL + 0] = (float)(mse * 0.25);
            out[OUT_SCAL + 1] = (float)mse;
            out[OUT_SCAL + 2] = perplexity;
            g_mse_sum = 0.0;
            g_done = 0;
        }
        g_hist[tid] = 0;
        g_hist[tid + 256] = 0;
    }
}

extern "C" void kernel_launch(void* const* d_in, const int* in_sizes, int n_in,
                              void* d_out, int out_size) {
    const float* latents  = (const float*)d_in[0];
    const float* codebook = (const float*)d_in[1];
    float* out = (float*)d_out;

    cudaFuncSetAttribute(vq_main_kernel,
                         cudaFuncAttributeMaxDynamicSharedMemorySize, SM_TOTAL);

    vq_main_kernel<<<GRID, TPB, SM_TOTAL>>>(latents, codebook, out);
}

// round 17
// speedup vs baseline: 1.4634x; 1.4634x over previous
#include <cuda_runtime.h>
#include <cuda_bf16.h>
#include <math_constants.h>
#include <cstdint>

// VectorQuantizer GB300: persistent kernel, mma.sync bf16 screen (4-way ILP,
// prefetched fragment-packed B) + 3-slot register stash + smem-codebook exact
// fp32 rescore + last-CTA finalize. latents [131072,64] f32, codebook [512,64] f32.
// out (f32): quantized_st[8388608] | codes[131072] | commitment | codebook_loss | perplexity

#define D        64
#define K        512
#define N_VEC    131072
#define TILE_M   128
#define N_TILES  (N_VEC / TILE_M)   // 1024
#define TPB      256
#define GRID     148

#define OUT_CODES (N_VEC * D)
#define OUT_SCAL  (OUT_CODES + N_VEC)
#define MARGIN    4e-3f
#define QMARGIN   (MARGIN + 4e-5f)

// ---- smem byte layout (220224 B -> 1 CTA/SM; B0/B1 are 32768 B EACH) ----
#define SM_RED     0                       // 8 f32 -> pad 64
#define SM_X2      64                      // 128 f32 -> 576
#define SM_BESTK   576                     // 128 i32 -> 1088
#define SM_C2      1088                    // 512 f32 -> 3136
#define SM_HIST    3136                    // 512 i32 -> 5184
#define SM_A_BF16  5184                    // 128 x 144B -> 23616
#define SM_B0      23616                   // 64 ntiles x 32 lanes x 16B = 32768 -> 56384
#define SM_B1      56384                   // 32768 -> 89152
#define SM_CB      89152                   // 512 x 64 f32 = 131072 -> 220224
#define SM_TOTAL   220224

__device__ double g_mse_sum;   // static zero-init; last CTA resets
__device__ int    g_hist[K];
__device__ int    g_done;

__device__ __forceinline__ void mma16816(float& c0, float& c1, float& c2, float& c3,
                                         uint32_t a0, uint32_t a1, uint32_t a2, uint32_t a3,
                                         uint32_t b0, uint32_t b1) {
    asm volatile(
        "mma.sync.aligned.m16n8k16.row.col.f32.bf16.bf16.f32 "
        "{%0,%1,%2,%3}, {%4,%5,%6,%7}, {%8,%9}, {%0,%1,%2,%3};"
        : "+f"(c0), "+f"(c1), "+f"(c2), "+f"(c3)
        : "r"(a0), "r"(a1), "r"(a2), "r"(a3), "r"(b0), "r"(b1));
}

// Exact fp32 distance — byte-for-byte the Round-1 formula (rel_err 0.0 lineage).
// Codebook row sourced from SMEM (identical values), x from global (L2-hot).
__device__ __forceinline__ float exact_d2_sm(const float* __restrict__ smcb,
                                             const float* __restrict__ x, float x2,
                                             const float* __restrict__ c2s, int col) {
    const float4* cr = (const float4*)(smcb + col * D);
    const float4* xr = (const float4*)x;
    float4 acc = make_float4(0.f, 0.f, 0.f, 0.f);
    #pragma unroll
    for (int i = 0; i < 16; i++) {
        float4 cc = cr[i];
        float4 xv = xr[i];
        acc.x = fmaf(xv.x, cc.x, acc.x); acc.y = fmaf(xv.y, cc.y, acc.y);
        acc.z = fmaf(xv.z, cc.z, acc.z); acc.w = fmaf(xv.w, cc.w, acc.w);
    }
    float dot = (acc.x + acc.y) + (acc.z + acc.w);
    return fmaf(-2.0f, dot, x2) + c2s[col];
}

#define SLOTF(t) __uint_as_float((t) & ~0x1FFu)
#define PUSH3(t0, t1, t2, s, col) do {                                       \
    uint32_t _pv = (__float_as_uint(s) & ~0x1FFu) | (unsigned)(col);         \
    float _fs = SLOTF(_pv);                                                  \
    if (_fs < SLOTF(t2)) {                                                   \
        if (_fs < SLOTF(t1)) {                                               \
            t2 = t1;                                                         \
            if (_fs < SLOTF(t0)) { t1 = t0; t0 = _pv; } else t1 = _pv;       \
        } else t2 = _pv;                                                     \
    }                                                                        \
} while (0)

// Rescore 3 slots vs threshold (or fallback rescan) — all smem-sourced.
// Returns packed key: (f32 bits of d2) << 32 | col  (d2 > 0 so order-safe).
__device__ __forceinline__ unsigned long long pick3(
    const float* __restrict__ smcb, const float* __restrict__ x,
    float x2, const float* __restrict__ c2s,
    uint32_t t0, uint32_t t1, uint32_t t2, float gthr, int tig)
{
    unsigned long long best = (0x7F800000ull << 32) | 0x1FFull;
    int nU = (SLOTF(t0) < gthr) + (SLOTF(t1) < gthr) + (SLOTF(t2) < gthr);
    if (nU < 3) {
        if (SLOTF(t0) < gthr) {
            int col = t0 & 0x1FF;
            float d2 = exact_d2_sm(smcb, x, x2, c2s, col);
            unsigned long long p = ((unsigned long long)__float_as_uint(d2) << 32) | (unsigned)col;
            if (p < best) best = p;
        }
        if (SLOTF(t1) < gthr) {
            int col = t1 & 0x1FF;
            float d2 = exact_d2_sm(smcb, x, x2, c2s, col);
            unsigned long long p = ((unsigned long long)__float_as_uint(d2) << 32) | (unsigned)col;
            if (p < best) best = p;
        }
        if (SLOTF(t2) < gthr) {
            int col = t2 & 0x1FF;
            float d2 = exact_d2_sm(smcb, x, x2, c2s, col);
            unsigned long long p = ((unsigned long long)__float_as_uint(d2) << 32) | (unsigned)col;
            if (p < best) best = p;
        }
    } else {   // stash saturated: rescan this thread's 128 cols (smem, rare)
        #pragma unroll 1
        for (int n = 0; n < 64; n++) {
            int col = n * 8 + tig * 2;
            float d2 = exact_d2_sm(smcb, x, x2, c2s, col);
            unsigned long long p = ((unsigned long long)__float_as_uint(d2) << 32) | (unsigned)col;
            if (p < best) best = p;
            d2 = exact_d2_sm(smcb, x, x2, c2s, col + 1);
            p = ((unsigned long long)__float_as_uint(d2) << 32) | (unsigned)(col + 1);
            if (p < best) best = p;
        }
    }
    return best;
}

__device__ __forceinline__ uint32_t pack2m(float a, float b) {
    __nv_bfloat162 h = __floats2bfloat162_rn(a, b);
    return *reinterpret_cast<uint32_t*>(&h);
}

__global__ __launch_bounds__(TPB) void vq_main_kernel(
    const float* __restrict__ latents,
    const float* __restrict__ codebook,
    float* __restrict__ out)
{
    extern __shared__ char smc[];
    __shared__ int   s_isLast;
    __shared__ float s_ent[256];

    float* red     = (float*)(smc + SM_RED);
    float* x2s     = (float*)(smc + SM_X2);
    int*   bestksm = (int*)(smc + SM_BESTK);
    float* c2s     = (float*)(smc + SM_C2);
    int*   histsm  = (int*)(smc + SM_HIST);
    float* smcb    = (float*)(smc + SM_CB);

    const int tid  = threadIdx.x;
    const int wid  = tid >> 5;
    const int lane = tid & 31;
    const int g    = lane >> 2;
    const int tig  = lane & 3;
    const int rowbase = wid * 16;

    // ---- one-time setup: hist, f32 codebook -> smem, fragment-B, c2 ----
    for (int k = tid; k < K; k += TPB) histsm[k] = 0;
    {
        const float4* gp = (const float4*)codebook;
        float4* sp = (float4*)smcb;
        #pragma unroll 4
        for (int i = tid; i < K * D / 4; i += TPB) sp[i] = gp[i];
    }
    __syncthreads();
    for (int idx = tid; idx < 64 * 32; idx += TPB) {
        int ntile = idx >> 5, ln = idx & 31;
        int gg = ln >> 2, tt = ln & 3;
        const float* cr = smcb + (ntile * 8 + gg) * D;
        uint4 u0, u1;
        u0.x = pack2m(-2.f * cr[ 0 + tt*2], -2.f * cr[ 0 + tt*2 + 1]);
        u0.y = pack2m(-2.f * cr[16 + tt*2], -2.f * cr[16 + tt*2 + 1]);
        u0.z = pack2m(-2.f * cr[32 + tt*2], -2.f * cr[32 + tt*2 + 1]);
        u0.w = pack2m(-2.f * cr[48 + tt*2], -2.f * cr[48 + tt*2 + 1]);
        u1.x = pack2m(-2.f * cr[ 8 + tt*2], -2.f * cr[ 8 + tt*2 + 1]);
        u1.y = pack2m(-2.f * cr[24 + tt*2], -2.f * cr[24 + tt*2 + 1]);
        u1.z = pack2m(-2.f * cr[40 + tt*2], -2.f * cr[40 + tt*2 + 1]);
        u1.w = pack2m(-2.f * cr[56 + tt*2], -2.f * cr[56 + tt*2 + 1]);
        *(uint4*)(smc + SM_B0 + idx * 16) = u0;
        *(uint4*)(smc + SM_B1 + idx * 16) = u1;
    }
    for (int k = tid; k < K; k += TPB) {   // Round-1-identical c2 formula
        const float4* row = (const float4*)(smcb + k * D);
        float4 a = make_float4(0.f, 0.f, 0.f, 0.f);
        #pragma unroll
        for (int i = 0; i < 16; i++) {
            float4 c = row[i];
            a.x = fmaf(c.x, c.x, a.x); a.y = fmaf(c.y, c.y, a.y);
            a.z = fmaf(c.z, c.z, a.z); a.w = fmaf(c.w, c.w, a.w);
        }
        c2s[k] = (a.x + a.y) + (a.z + a.w);
    }
    __syncthreads();

    float cta_msq = 0.f;

    for (int tile = blockIdx.x; tile < N_TILES; tile += GRID) {
        const float* tlat = latents + (size_t)tile * (TILE_M * D);

        // ---- 1. latent tile -> bf16 A operand in smem ----
        {
            const float4* gp = (const float4*)tlat;
            #pragma unroll
            for (int i = 0; i < 8; i++) {
                int idx = i * TPB + tid;
                float4 v = gp[idx];
                int row = idx >> 4, col = idx & 15;
                uint2 u;
                u.x = pack2m(v.x, v.y);
                u.y = pack2m(v.z, v.w);
                *(uint2*)(smc + SM_A_BF16 + row * 144 + col * 8) = u;
            }
        }

        // ---- 2. x2 per row (R1-identical chain) ----
        if (tid < TILE_M) {
            const float4* my = (const float4*)(tlat + tid * D);
            float4 a = make_float4(0.f, 0.f, 0.f, 0.f);
            #pragma unroll
            for (int i = 0; i < 16; i++) {
                float4 v = my[i];
                a.x = fmaf(v.x, v.x, a.x); a.y = fmaf(v.y, v.y, a.y);
                a.z = fmaf(v.z, v.z, a.z); a.w = fmaf(v.w, v.w, a.w);
            }
            x2s[tid] = (a.x + a.y) + (a.z + a.w);
        }
        __syncthreads();

        // ---- 3. A fragments for this warp's 16 rows ----
        uint32_t af[4][4];
        #pragma unroll
        for (int kt = 0; kt < 4; kt++) {
            int kb = kt * 32 + tig * 4;
            af[kt][0] = *(const uint32_t*)(smc + SM_A_BF16 + (rowbase + g)     * 144 + kb);
            af[kt][1] = *(const uint32_t*)(smc + SM_A_BF16 + (rowbase + g + 8) * 144 + kb);
            af[kt][2] = *(const uint32_t*)(smc + SM_A_BF16 + (rowbase + g)     * 144 + kb + 16);
            af[kt][3] = *(const uint32_t*)(smc + SM_A_BF16 + (rowbase + g + 8) * 144 + kb + 16);
        }

        // ---- 4. screen: 4-way-ILP HMMA + prefetched B + 3-slot stash ----
        float runA = CUDART_INF_F, runB = CUDART_INF_F;
        uint32_t a0 = 0x7F800000u, a1 = 0x7F800000u, a2 = 0x7F800000u;
        uint32_t e0 = 0x7F800000u, e1 = 0x7F800000u, e2 = 0x7F800000u;
        uint4 w0 = *(const uint4*)(smc + SM_B0 + lane * 16);
        uint4 w1 = *(const uint4*)(smc + SM_B1 + lane * 16);
        #pragma unroll 4
        for (int ntile = 0; ntile < 64; ntile++) {
            uint4 n0, n1;
            if (ntile < 63) {
                n0 = *(const uint4*)(smc + SM_B0 + ((ntile + 1) * 32 + lane) * 16);
                n1 = *(const uint4*)(smc + SM_B1 + ((ntile + 1) * 32 + lane) * 16);
            }
            float p0 = 0.f, p1 = 0.f, p2 = 0.f, p3 = 0.f;
            float q0 = 0.f, q1 = 0.f, q2 = 0.f, q3 = 0.f;
            float r0 = 0.f, r1 = 0.f, r2 = 0.f, r3 = 0.f;
            float u0 = 0.f, u1 = 0.f, u2 = 0.f, u3 = 0.f;
            mma16816(p0, p1, p2, p3, af[0][0], af[0][1], af[0][2], af[0][3], w0.x, w1.x);
            mma16816(q0, q1, q2, q3, af[1][0], af[1][1], af[1][2], af[1][3], w0.y, w1.y);
            mma16816(r0, r1, r2, r3, af[2][0], af[2][1], af[2][2], af[2][3], w0.z, w1.z);
            mma16816(u0, u1, u2, u3, af[3][0], af[3][1], af[3][2], af[3][3], w0.w, w1.w);
            float s0 = (p0 + q0) + (r0 + u0), s1 = (p1 + q1) + (r1 + u1);
            float s2 = (p2 + q2) + (r2 + u2), s3 = (p3 + q3) + (r3 + u3);
            int col0 = ntile * 8 + tig * 2, col1 = col0 + 1;
            runA = fminf(runA, fminf(s0, s1));
            runB = fminf(runB, fminf(s2, s3));
            float thrA = runA + MARGIN, thrB = runB + MARGIN;
            if (s0 < thrA) PUSH3(a0, a1, a2, s0, col0);
            if (s1 < thrA) PUSH3(a0, a1, a2, s1, col1);
            if (s2 < thrB) PUSH3(e0, e1, e2, s2, col0);
            if (s3 < thrB) PUSH3(e0, e1, e2, s3, col1);
            w0 = n0; w1 = n1;
        }

        // ---- 5. final row min (quad) + rescore (smem codebook) ----
        #pragma unroll
        for (int off = 1; off <= 2; off <<= 1) {
            runA = fminf(runA, __shfl_xor_sync(0xFFFFFFFFu, runA, off));
            runB = fminf(runB, __shfl_xor_sync(0xFFFFFFFFu, runB, off));
        }
        const int rowA = rowbase + g, rowB = rowbase + g + 8;
        unsigned long long pA = pick3(smcb, tlat + rowA * D, x2s[rowA], c2s,
                                      a0, a1, a2, runA + QMARGIN, tig);
        unsigned long long pB = pick3(smcb, tlat + rowB * D, x2s[rowB], c2s,
                                      e0, e1, e2, runB + QMARGIN, tig);
        #pragma unroll
        for (int off = 1; off <= 2; off <<= 1) {
            unsigned long long o = __shfl_xor_sync(0xFFFFFFFFu, pA, off);
            if (o < pA) pA = o;
            o = __shfl_xor_sync(0xFFFFFFFFu, pB, off);
            if (o < pB) pB = o;
        }
        if (tig == 0) {
            bestksm[rowA] = (int)(pA & 0x1FF);
            bestksm[rowB] = (int)(pB & 0x1FF);
        }
        __syncthreads();

        // ---- 6. codes + histogram ----
        if (tid < TILE_M) {
            int bk = bestksm[tid];
            out[OUT_CODES + tile * TILE_M + tid] = (float)bk;
            atomicAdd(&histsm[bk], 1);
        }

        // ---- 7. quantized_st + mse (codebook from smem, x from L2) ----
        float msq = 0.f;
        {
            float4* og = (float4*)out + (size_t)tile * (TILE_M * D / 4);
            const float4* gp = (const float4*)tlat;
            #pragma unroll
            for (int i = 0; i < 8; i++) {
                int idx = i * TPB + tid;
                int row = idx >> 4, col = idx & 15;
                float4 xv = gp[idx];
                float4 c = ((const float4*)(smcb + bestksm[row] * D))[col];
                float4 o;
                o.x = xv.x + (c.x - xv.x); o.y = xv.y + (c.y - xv.y);
                o.z = xv.z + (c.z - xv.z); o.w = xv.w + (c.w - xv.w);
                float dx = xv.x - c.x; msq = fmaf(dx, dx, msq);
                dx = xv.y - c.y; msq = fmaf(dx, dx, msq);
                dx = xv.z - c.z; msq = fmaf(dx, dx, msq);
                dx = xv.w - c.w; msq = fmaf(dx, dx, msq);
                og[idx] = o;
            }
        }

        // ---- 8. msq block-reduce ----
        #pragma unroll
        for (int s = 16; s > 0; s >>= 1) msq += __shfl_xor_sync(0xFFFFFFFFu, msq, s);
        if (lane == 0) red[wid] = msq;
        __syncthreads();
        if (tid == 0) {
            float bsum = 0.f;
            #pragma unroll
            for (int w = 0; w < 8; w++) bsum += red[w];
            cta_msq += bsum;
        }
        __syncthreads();   // protect smem reuse next tile
    }

    // ---- flush per-CTA hist + mse ----
    for (int k = tid; k < K; k += TPB) {
        int h = histsm[k];
        if (h) atomicAdd(&g_hist[k], h);
    }
    if (tid == 0) atomicAdd(&g_mse_sum, (double)cta_msq);

    // ---- last-CTA finalize (scalars + reset for graph replay) ----
    __threadfence();
    if (tid == 0) {
        int c = atomicAdd(&g_done, 1);
        s_isLast = (c == GRID - 1);
    }
    __syncthreads();
    if (s_isLast) {
        float cnt0 = (float)g_hist[tid];
        float p0v  = cnt0 / (float)N_VEC;
        float t0v  = -p0v * logf(p0v + 1e-10f);
        float cnt1 = (float)g_hist[tid + 256];
        float p1v  = cnt1 / (float)N_VEC;
        float t1v  = -p1v * logf(p1v + 1e-10f);
        s_ent[tid] = t0v + t1v;
        __syncthreads();
        for (int s = 128; s > 0; s >>= 1) {
            if (tid < s) s_ent[tid] += s_ent[tid + s];
            __syncthreads();
        }
        if (tid == 0) {
            float perplexity = expf(s_ent[0]);
            double mse = g_mse_sum / (double)(N_VEC * D);
            out[OUT_SCAL + 0] = (float)(mse * 0.25);
            out[OUT_SCAL + 1] = (float)mse;
            out[OUT_SCAL + 2] = perplexity;
            g_mse_sum = 0.0;
            g_done = 0;
        }
        g_hist[tid] = 0;
        g_hist[tid + 256] = 0;
    }
}

extern "C" void kernel_launch(void* const* d_in, const int* in_sizes, int n_in,
                              void* d_out, int out_size) {
    const float* latents  = (const float*)d_in[0];
    const float* codebook = (const float*)d_in[1];
    float* out = (float*)d_out;

    cudaFuncSetAttribute(vq_main_kernel,
                         cudaFuncAttributeMaxDynamicSharedMemorySize, SM_TOTAL);

    vq_main_kernel<<<GRID, TPB, SM_TOTAL>>>(latents, codebook, out);
}